// round 1
// baseline (speedup 1.0000x reference)
#include <cuda_runtime.h>
#include <math.h>

#define BB 2
#define TT 2048
#define DD 1024
#define HH 16
#define HDIM 64
#define MROWS (BB * TT)   // 4096

// Scratch (static device globals -- no allocation in kernel_launch)
__device__ float g_qkv[(size_t)MROWS * 3 * DD];   // [4096, 3072]
__device__ float g_yatt[(size_t)MROWS * DD];      // [4096, 1024]

// ---------------------------------------------------------------------------
// Tiled SGEMM body: C[m,n] = sum_k A[m,k]*W[n,k] + bias[n]
// BM=BN=64, BK=16, 256 threads, 4x4 microtile per thread.
// M assumed multiple of 64 (4096), N multiple of 64, K multiple of 16.
// ---------------------------------------------------------------------------
__device__ __forceinline__ void sgemm_body(const float* __restrict__ A,
                                           const float* __restrict__ W,
                                           const float* __restrict__ bias,
                                           float* __restrict__ C,
                                           int N, int K) {
    __shared__ float As[16][64];
    __shared__ float Ws[16][64];

    const int tid = threadIdx.x;
    const int tx = tid & 15;        // 0..15 -> n
    const int ty = tid >> 4;        // 0..15 -> m
    const int m0 = blockIdx.y * 64;
    const int n0 = blockIdx.x * 64;

    const int lrow = tid >> 2;          // 0..63
    const int lseg = (tid & 3) << 2;    // 0,4,8,12

    float acc[4][4] = {};

    for (int k0 = 0; k0 < K; k0 += 16) {
        float4 av = *(const float4*)(A + (size_t)(m0 + lrow) * K + k0 + lseg);
        float4 wv = *(const float4*)(W + (size_t)(n0 + lrow) * K + k0 + lseg);
        As[lseg + 0][lrow] = av.x; As[lseg + 1][lrow] = av.y;
        As[lseg + 2][lrow] = av.z; As[lseg + 3][lrow] = av.w;
        Ws[lseg + 0][lrow] = wv.x; Ws[lseg + 1][lrow] = wv.y;
        Ws[lseg + 2][lrow] = wv.z; Ws[lseg + 3][lrow] = wv.w;
        __syncthreads();

        #pragma unroll
        for (int kk = 0; kk < 16; kk++) {
            float a[4], w[4];
            #pragma unroll
            for (int i = 0; i < 4; i++) a[i] = As[kk][ty * 4 + i];
            #pragma unroll
            for (int j = 0; j < 4; j++) w[j] = Ws[kk][tx * 4 + j];
            #pragma unroll
            for (int i = 0; i < 4; i++)
                #pragma unroll
                for (int j = 0; j < 4; j++)
                    acc[i][j] += a[i] * w[j];
        }
        __syncthreads();
    }

    const int n = n0 + tx * 4;
    float4 bv = *(const float4*)(bias + n);
    #pragma unroll
    for (int i = 0; i < 4; i++) {
        float4 r;
        r.x = acc[i][0] + bv.x;
        r.y = acc[i][1] + bv.y;
        r.z = acc[i][2] + bv.z;
        r.w = acc[i][3] + bv.w;
        *(float4*)(C + (size_t)(m0 + ty * 4 + i) * N + n) = r;
    }
}

__global__ __launch_bounds__(256) void qkv_gemm_kernel(const float* __restrict__ x,
                                                       const float* __restrict__ w_qkv,
                                                       const float* __restrict__ b_qkv) {
    sgemm_body(x, w_qkv, b_qkv, g_qkv, 3 * DD, DD);
}

__global__ __launch_bounds__(256) void proj_gemm_kernel(const float* __restrict__ w_proj,
                                                        const float* __restrict__ b_proj,
                                                        float* __restrict__ out) {
    sgemm_body(g_yatt, w_proj, b_proj, out, DD, DD);
}

// ---------------------------------------------------------------------------
// Flash attention (fp32, causal). One block = (q-tile of 64, head, batch).
// 256 threads = 8 warps; warp w owns query rows w*8 .. w*8+7 of the tile.
// K tile is XOR-swizzled in smem for conflict-free column-major reads.
// ---------------------------------------------------------------------------
__global__ __launch_bounds__(256) void flash_attn_kernel() {
    const int qt = blockIdx.x;   // 0..31
    const int h  = blockIdx.y;   // 0..15
    const int b  = blockIdx.z;   // 0..1

    __shared__ float Qs[64][64];
    __shared__ float Ks[64][64];  // swizzled: Ks[c][d ^ (c & 31)]
    __shared__ float Vs[64][64];

    const int tid  = threadIdx.x;
    const int warp = tid >> 5;
    const int lane = tid & 31;

    const int q0 = qt * 64;
    const float scale = 0.125f;  // 1/sqrt(64)

    // Load Q tile (scale folded in)
    for (int i = tid; i < 64 * 64; i += 256) {
        int r = i >> 6, d = i & 63;
        Qs[r][d] = g_qkv[((size_t)(b * TT + q0 + r)) * (3 * DD) + h * HDIM + d] * scale;
    }

    float m[8], l[8], o0[8], o1[8];
    #pragma unroll
    for (int rr = 0; rr < 8; rr++) {
        m[rr] = -3.0e38f; l[rr] = 0.f; o0[rr] = 0.f; o1[rr] = 0.f;
    }

    const int nkt = qt + 1;  // causal: only tiles up to the diagonal
    for (int kt = 0; kt < nkt; kt++) {
        const int k0 = kt * 64;
        __syncthreads();  // previous tile's Ks/Vs fully consumed
        for (int i = tid; i < 64 * 64; i += 256) {
            int r = i >> 6, d = i & 63;
            size_t base = ((size_t)(b * TT + k0 + r)) * (3 * DD) + h * HDIM + d;
            Ks[r][d ^ (r & 31)] = g_qkv[base + DD];
            Vs[r][d]            = g_qkv[base + 2 * DD];
        }
        __syncthreads();

        const bool diag = (kt == qt);

        #pragma unroll 1
        for (int rr = 0; rr < 8; rr++) {
            const int r = warp * 8 + rr;

            float s0 = 0.f, s1 = 0.f;
            #pragma unroll
            for (int d = 0; d < 64; d++) {
                float qv = Qs[r][d];
                s0 = fmaf(qv, Ks[lane][d ^ lane], s0);
                s1 = fmaf(qv, Ks[lane + 32][d ^ lane], s1);
            }

            if (diag) {
                const int qg = q0 + r;
                if (k0 + lane > qg)      s0 = -3.0e38f;
                if (k0 + lane + 32 > qg) s1 = -3.0e38f;
            }

            float rmax = fmaxf(s0, s1);
            #pragma unroll
            for (int off = 16; off; off >>= 1)
                rmax = fmaxf(rmax, __shfl_xor_sync(0xffffffffu, rmax, off));

            const float mnew = fmaxf(m[rr], rmax);
            const float corr = __expf(m[rr] - mnew);  // 0 on first tile
            const float p0 = __expf(s0 - mnew);
            const float p1 = __expf(s1 - mnew);

            float rs = p0 + p1;
            #pragma unroll
            for (int off = 16; off; off >>= 1)
                rs += __shfl_xor_sync(0xffffffffu, rs, off);

            l[rr] = l[rr] * corr + rs;
            m[rr] = mnew;

            float a0 = o0[rr] * corr;
            float a1 = o1[rr] * corr;
            #pragma unroll
            for (int cc = 0; cc < 32; cc++) {
                const float pa = __shfl_sync(0xffffffffu, p0, cc);
                const float pb = __shfl_sync(0xffffffffu, p1, cc);
                a0 = fmaf(pa, Vs[cc][lane],      a0);
                a0 = fmaf(pb, Vs[cc + 32][lane], a0);
                a1 = fmaf(pa, Vs[cc][lane + 32],      a1);
                a1 = fmaf(pb, Vs[cc + 32][lane + 32], a1);
            }
            o0[rr] = a0;
            o1[rr] = a1;
        }
    }

    // Normalize and write attention output back in [B,T,D] layout
    #pragma unroll
    for (int rr = 0; rr < 8; rr++) {
        const int r = warp * 8 + rr;
        const float inv = 1.0f / l[rr];
        size_t base = ((size_t)(b * TT + q0 + r)) * DD + h * HDIM;
        g_yatt[base + lane]      = o0[rr] * inv;
        g_yatt[base + lane + 32] = o1[rr] * inv;
    }
}

// ---------------------------------------------------------------------------
// Launch: QKV GEMM -> flash attention -> output projection
// Inputs (metadata order): x, attn_mask(ignored; causal is static),
//                          w_qkv, b_qkv, w_proj, b_proj
// ---------------------------------------------------------------------------
extern "C" void kernel_launch(void* const* d_in, const int* in_sizes, int n_in,
                              void* d_out, int out_size) {
    const float* x      = (const float*)d_in[0];
    const float* w_qkv  = (const float*)d_in[2];
    const float* b_qkv  = (const float*)d_in[3];
    const float* w_proj = (const float*)d_in[4];
    const float* b_proj = (const float*)d_in[5];
    float* out = (float*)d_out;

    // QKV projection: [4096,1024] x [3072,1024]^T -> g_qkv [4096,3072]
    {
        dim3 grid((3 * DD) / 64, MROWS / 64);
        qkv_gemm_kernel<<<grid, 256>>>(x, w_qkv, b_qkv);
    }

    // Flash attention: g_qkv -> g_yatt [4096,1024]
    {
        dim3 grid(TT / 64, HH, BB);
        flash_attn_kernel<<<grid, 256>>>();
    }

    // Output projection: [4096,1024] x [1024,1024]^T -> out
    {
        dim3 grid(DD / 64, MROWS / 64);
        proj_gemm_kernel<<<grid, 256>>>(w_proj, b_proj, out);
    }
}

// round 2
// speedup vs baseline: 1.8491x; 1.8491x over previous
#include <cuda_runtime.h>
#include <math.h>

#define BB 2
#define TT 2048
#define DD 1024
#define HH 16
#define HDIM 64
#define MROWS (BB * TT)   // 4096

typedef unsigned long long u64;

// Scratch (static device globals -- no allocation in kernel_launch)
__device__ float g_qkv[(size_t)MROWS * 3 * DD];   // [4096, 3072]
__device__ float g_yatt[(size_t)MROWS * DD];      // [4096, 1024]

// ---------------------------------------------------------------------------
// packed fp32x2 helpers (Blackwell FFMA2 -- 2x fp32 FMA throughput)
// ---------------------------------------------------------------------------
__device__ __forceinline__ u64 pack2(float x, float y) {
    u64 r;
    asm("mov.b64 %0, {%1, %2};" : "=l"(r) : "f"(x), "f"(y));
    return r;
}
__device__ __forceinline__ void unpack2(u64 v, float& x, float& y) {
    asm("mov.b64 {%0, %1}, %2;" : "=f"(x), "=f"(y) : "l"(v));
}
__device__ __forceinline__ void ffma2(u64& d, u64 a, u64 b) {
    asm("fma.rn.f32x2 %0, %1, %2, %0;" : "+l"(d) : "l"(a), "l"(b));
}

// ---------------------------------------------------------------------------
// SGEMM: C[m,n] = sum_k A[m,k]*W[n,k] + bias[n]
// 128x128x16 tiles, 256 threads, 8x8 microtile, double-buffered smem, FFMA2.
// M,N multiples of 128; K multiple of 16.
// ---------------------------------------------------------------------------
__device__ __forceinline__ void gemm128_body(const float* __restrict__ A,
                                             const float* __restrict__ W,
                                             const float* __restrict__ bias,
                                             float* __restrict__ C,
                                             int N, int K) {
    __shared__ __align__(16) float As[2][16][132];
    __shared__ __align__(16) float Ws[2][16][132];

    const int tid = threadIdx.x;
    const int tx = tid & 15;          // n microtile
    const int ty = tid >> 4;          // m microtile
    const int m0 = blockIdx.y * 128;
    const int n0 = blockIdx.x * 128;

    const int row = tid >> 2;         // 0..63 (loader row; +64 for second half)
    const int sg  = (tid & 3) * 4;    // k segment 0,4,8,12

    const float* Ap = A + (size_t)(m0 + row) * K + sg;
    const float* Wp = W + (size_t)(n0 + row) * K + sg;
    const size_t half = (size_t)64 * K;

    u64 acc[8][4];
    #pragma unroll
    for (int i = 0; i < 8; i++)
        #pragma unroll
        for (int j = 0; j < 4; j++) acc[i][j] = 0ull;

    // prologue: load stage 0
    float4 a0v = *(const float4*)(Ap);
    float4 a1v = *(const float4*)(Ap + half);
    float4 w0v = *(const float4*)(Wp);
    float4 w1v = *(const float4*)(Wp + half);

    As[0][sg + 0][row] = a0v.x; As[0][sg + 1][row] = a0v.y;
    As[0][sg + 2][row] = a0v.z; As[0][sg + 3][row] = a0v.w;
    As[0][sg + 0][row + 64] = a1v.x; As[0][sg + 1][row + 64] = a1v.y;
    As[0][sg + 2][row + 64] = a1v.z; As[0][sg + 3][row + 64] = a1v.w;
    Ws[0][sg + 0][row] = w0v.x; Ws[0][sg + 1][row] = w0v.y;
    Ws[0][sg + 2][row] = w0v.z; Ws[0][sg + 3][row] = w0v.w;
    Ws[0][sg + 0][row + 64] = w1v.x; Ws[0][sg + 1][row + 64] = w1v.y;
    Ws[0][sg + 2][row + 64] = w1v.z; Ws[0][sg + 3][row + 64] = w1v.w;
    __syncthreads();

    const int NT = K / 16;
    int buf = 0;
    for (int kt = 0; kt < NT; kt++) {
        if (kt + 1 < NT) {
            const float* Ap2 = Ap + (kt + 1) * 16;
            const float* Wp2 = Wp + (kt + 1) * 16;
            a0v = *(const float4*)(Ap2);
            a1v = *(const float4*)(Ap2 + half);
            w0v = *(const float4*)(Wp2);
            w1v = *(const float4*)(Wp2 + half);
        }

        #pragma unroll
        for (int kk = 0; kk < 16; kk++) {
            float4 a_lo = *(const float4*)&As[buf][kk][ty * 4];
            float4 a_hi = *(const float4*)&As[buf][kk][64 + ty * 4];
            u64 b0 = *(const u64*)&Ws[buf][kk][tx * 4];
            u64 b1 = *(const u64*)&Ws[buf][kk][tx * 4 + 2];
            u64 b2 = *(const u64*)&Ws[buf][kk][64 + tx * 4];
            u64 b3 = *(const u64*)&Ws[buf][kk][64 + tx * 4 + 2];
            float av[8] = {a_lo.x, a_lo.y, a_lo.z, a_lo.w,
                           a_hi.x, a_hi.y, a_hi.z, a_hi.w};
            #pragma unroll
            for (int i = 0; i < 8; i++) {
                u64 ad = pack2(av[i], av[i]);
                ffma2(acc[i][0], ad, b0);
                ffma2(acc[i][1], ad, b1);
                ffma2(acc[i][2], ad, b2);
                ffma2(acc[i][3], ad, b3);
            }
        }

        if (kt + 1 < NT) {
            const int nb = buf ^ 1;
            As[nb][sg + 0][row] = a0v.x; As[nb][sg + 1][row] = a0v.y;
            As[nb][sg + 2][row] = a0v.z; As[nb][sg + 3][row] = a0v.w;
            As[nb][sg + 0][row + 64] = a1v.x; As[nb][sg + 1][row + 64] = a1v.y;
            As[nb][sg + 2][row + 64] = a1v.z; As[nb][sg + 3][row + 64] = a1v.w;
            Ws[nb][sg + 0][row] = w0v.x; Ws[nb][sg + 1][row] = w0v.y;
            Ws[nb][sg + 2][row] = w0v.z; Ws[nb][sg + 3][row] = w0v.w;
            Ws[nb][sg + 0][row + 64] = w1v.x; Ws[nb][sg + 1][row + 64] = w1v.y;
            Ws[nb][sg + 2][row + 64] = w1v.z; Ws[nb][sg + 3][row + 64] = w1v.w;
        }
        __syncthreads();
        buf ^= 1;
    }

    // epilogue: unpack, add bias, store
    float4 bv0 = *(const float4*)(bias + n0 + tx * 4);
    float4 bv1 = *(const float4*)(bias + n0 + 64 + tx * 4);
    #pragma unroll
    for (int i = 0; i < 8; i++) {
        const int m = m0 + ((i < 4) ? (ty * 4 + i) : (64 + ty * 4 + i - 4));
        float4 r0, r1;
        unpack2(acc[i][0], r0.x, r0.y);
        unpack2(acc[i][1], r0.z, r0.w);
        unpack2(acc[i][2], r1.x, r1.y);
        unpack2(acc[i][3], r1.z, r1.w);
        r0.x += bv0.x; r0.y += bv0.y; r0.z += bv0.z; r0.w += bv0.w;
        r1.x += bv1.x; r1.y += bv1.y; r1.z += bv1.z; r1.w += bv1.w;
        *(float4*)(C + (size_t)m * N + n0 + tx * 4) = r0;
        *(float4*)(C + (size_t)m * N + n0 + 64 + tx * 4) = r1;
    }
}

__global__ __launch_bounds__(256) void qkv_gemm_kernel(const float* __restrict__ x,
                                                       const float* __restrict__ w_qkv,
                                                       const float* __restrict__ b_qkv) {
    gemm128_body(x, w_qkv, b_qkv, g_qkv, 3 * DD, DD);
}

__global__ __launch_bounds__(256) void proj_gemm_kernel(const float* __restrict__ w_proj,
                                                        const float* __restrict__ b_proj,
                                                        float* __restrict__ out) {
    gemm128_body(g_yatt, w_proj, b_proj, out, DD, DD);
}

// ---------------------------------------------------------------------------
// Flash attention (fp32, causal). One block = (q-tile of 64, head, batch).
// 8 warps; warp w owns query rows w*8..w*8+7. Scores/outputs in registers,
// P staged in warp-private smem region for the PV accumulation.
// ---------------------------------------------------------------------------
__global__ __launch_bounds__(256) void flash_attn_kernel() {
    const int qt = blockIdx.x;
    const int h  = blockIdx.y;
    const int b  = blockIdx.z;

    extern __shared__ __align__(16) float sm[];
    float (*Qs)[64] = (float(*)[64])(sm);
    float (*Ks)[64] = (float(*)[64])(sm + 64 * 64);       // swizzled [r][d ^ (r&31)]
    float (*Vs)[64] = (float(*)[64])(sm + 2 * 64 * 64);
    float (*Ps)[64] = (float(*)[64])(sm + 3 * 64 * 64);   // warp-private rows

    const int tid  = threadIdx.x;
    const int warp = tid >> 5;
    const int lane = tid & 31;
    const int r_base = warp * 8;
    const int q0 = qt * 64;
    const float scale = 0.125f;

    for (int i = tid; i < 64 * 64; i += 256) {
        int r = i >> 6, d = i & 63;
        Qs[r][d] = g_qkv[((size_t)(b * TT + q0 + r)) * (3 * DD) + h * HDIM + d] * scale;
    }

    float m[8], l[8], o0[8], o1[8];
    #pragma unroll
    for (int rr = 0; rr < 8; rr++) {
        m[rr] = -3.0e38f; l[rr] = 0.f; o0[rr] = 0.f; o1[rr] = 0.f;
    }

    for (int kt = 0; kt <= qt; kt++) {
        const int k0 = kt * 64;
        __syncthreads();   // Q/prev-P consumed; safe to overwrite K/V
        for (int i = tid; i < 64 * 64; i += 256) {
            int r = i >> 6, d = i & 63;
            size_t base = ((size_t)(b * TT + k0 + r)) * (3 * DD) + h * HDIM + d;
            Ks[r][d ^ (r & 31)] = g_qkv[base + DD];
            Vs[r][d]            = g_qkv[base + 2 * DD];
        }
        __syncthreads();

        // ---- S = Q K^T (per-warp 8x64 tile in registers) ----
        float s0[8], s1[8];
        #pragma unroll
        for (int rr = 0; rr < 8; rr++) { s0[rr] = 0.f; s1[rr] = 0.f; }

        #pragma unroll 4
        for (int d4 = 0; d4 < 64; d4 += 4) {
            float ka[4], kb[4];
            #pragma unroll
            for (int j = 0; j < 4; j++) {
                ka[j] = Ks[lane][(d4 + j) ^ lane];
                kb[j] = Ks[lane + 32][(d4 + j) ^ lane];
            }
            #pragma unroll
            for (int rr = 0; rr < 8; rr++) {
                float4 qv = *(const float4*)&Qs[r_base + rr][d4];
                s0[rr] = fmaf(qv.x, ka[0], fmaf(qv.y, ka[1],
                         fmaf(qv.z, ka[2], fmaf(qv.w, ka[3], s0[rr]))));
                s1[rr] = fmaf(qv.x, kb[0], fmaf(qv.y, kb[1],
                         fmaf(qv.z, kb[2], fmaf(qv.w, kb[3], s1[rr]))));
            }
        }

        // ---- online softmax + stage P ----
        const bool diag = (kt == qt);
        #pragma unroll
        for (int rr = 0; rr < 8; rr++) {
            const int r = r_base + rr;
            float v0 = s0[rr], v1 = s1[rr];
            if (diag) {
                const int qg = q0 + r;
                if (k0 + lane > qg)      v0 = -3.0e38f;
                if (k0 + lane + 32 > qg) v1 = -3.0e38f;
            }
            float rmax = fmaxf(v0, v1);
            #pragma unroll
            for (int off = 16; off; off >>= 1)
                rmax = fmaxf(rmax, __shfl_xor_sync(0xffffffffu, rmax, off));

            const float mnew = fmaxf(m[rr], rmax);
            const float corr = __expf(m[rr] - mnew);
            const float p0 = __expf(v0 - mnew);
            const float p1 = __expf(v1 - mnew);

            float rs = p0 + p1;
            #pragma unroll
            for (int off = 16; off; off >>= 1)
                rs += __shfl_xor_sync(0xffffffffu, rs, off);

            l[rr] = l[rr] * corr + rs;
            m[rr] = mnew;
            o0[rr] *= corr;
            o1[rr] *= corr;
            Ps[r][lane]      = p0;
            Ps[r][lane + 32] = p1;
        }
        __syncwarp();

        // ---- O += P V (per-warp, P from warp-private smem) ----
        #pragma unroll 4
        for (int c4 = 0; c4 < 64; c4 += 4) {
            float va[4], vb[4];
            #pragma unroll
            for (int j = 0; j < 4; j++) {
                va[j] = Vs[c4 + j][lane];
                vb[j] = Vs[c4 + j][lane + 32];
            }
            #pragma unroll
            for (int rr = 0; rr < 8; rr++) {
                float4 pv = *(const float4*)&Ps[r_base + rr][c4];
                o0[rr] = fmaf(pv.x, va[0], fmaf(pv.y, va[1],
                         fmaf(pv.z, va[2], fmaf(pv.w, va[3], o0[rr]))));
                o1[rr] = fmaf(pv.x, vb[0], fmaf(pv.y, vb[1],
                         fmaf(pv.z, vb[2], fmaf(pv.w, vb[3], o1[rr]))));
            }
        }
    }

    // normalize and write back in [B,T,D] layout
    #pragma unroll
    for (int rr = 0; rr < 8; rr++) {
        const int r = r_base + rr;
        const float inv = 1.0f / l[rr];
        size_t base = ((size_t)(b * TT + q0 + r)) * DD + h * HDIM;
        g_yatt[base + lane]      = o0[rr] * inv;
        g_yatt[base + lane + 32] = o1[rr] * inv;
    }
}

// ---------------------------------------------------------------------------
// Launch: QKV GEMM -> flash attention -> output projection
// Inputs (metadata order): x, attn_mask(ignored; causal static),
//                          w_qkv, b_qkv, w_proj, b_proj
// ---------------------------------------------------------------------------
extern "C" void kernel_launch(void* const* d_in, const int* in_sizes, int n_in,
                              void* d_out, int out_size) {
    const float* x      = (const float*)d_in[0];
    const float* w_qkv  = (const float*)d_in[2];
    const float* b_qkv  = (const float*)d_in[3];
    const float* w_proj = (const float*)d_in[4];
    const float* b_proj = (const float*)d_in[5];
    float* out = (float*)d_out;

    // QKV projection: [4096,1024] x [3072,1024]^T -> g_qkv [4096,3072]
    {
        dim3 grid((3 * DD) / 128, MROWS / 128);
        qkv_gemm_kernel<<<grid, 256>>>(x, w_qkv, b_qkv);
    }

    // Flash attention: g_qkv -> g_yatt [4096,1024]
    {
        static int smem_set = 0;
        if (!smem_set) {
            cudaFuncSetAttribute(flash_attn_kernel,
                                 cudaFuncAttributeMaxDynamicSharedMemorySize, 65536);
            smem_set = 1;
        }
        dim3 grid(TT / 64, HH, BB);
        flash_attn_kernel<<<grid, 256, 65536>>>();
    }

    // Output projection: [4096,1024] x [1024,1024]^T -> out
    {
        dim3 grid(DD / 128, MROWS / 128);
        proj_gemm_kernel<<<grid, 256>>>(w_proj, b_proj, out);
    }
}